// round 1
// baseline (speedup 1.0000x reference)
#include <cuda_runtime.h>
#include <cuda_bf16.h>

// Problem constants (fixed by the reference)
#define B_  2
#define L_  2048
#define DM_ 1024
#define DS_ 16
#define DC_ 4
#define DI_ 2048          // EXP_ * DM_
#define MTOK (B_ * L_)    // 4096 tokens
#define NPROJ (2 * DS_ + 1)  // 33

// ---------------- scratch (static device globals; no allocs allowed) -------
__device__ float g_xz[MTOK * 2 * DI_];   // in-proj output [4096, 4096]  (u | z)
__device__ float g_ug[MTOK * DI_];       // gated conv output [4096, 2048]
__device__ float g_proj[MTOK * NPROJ];   // x-proj output [4096, 33]
__device__ float g_y[MTOK * DI_];        // scan output [4096, 2048]

// ---------------------------------------------------------------------------
// SGEMM: C[M,N] = A[M,K] @ B[N,K]^T  (both operands K-contiguous, fp32)
// Block tile 128x128, K-tile 8, 256 threads, 8x8 per-thread microtile.
// Requires M%128==0, N%128==0, K%8==0 (true for all shapes here).
// ---------------------------------------------------------------------------
#define BM 128
#define BN 128
#define BK 8
#define TM 8
#define TN 8

__global__ __launch_bounds__(256)
void sgemm_nt(const float* __restrict__ A, const float* __restrict__ Bm,
              float* __restrict__ C, int M, int N, int K) {
    __shared__ float As[BK][BM];
    __shared__ float Bs[BK][BN];

    const int bm = blockIdx.y * BM;
    const int bn = blockIdx.x * BN;
    const int tid = threadIdx.x;           // 0..255
    const int tx = tid & 15;               // 0..15 -> N dim
    const int ty = tid >> 4;               // 0..15 -> M dim

    // Each thread loads one float4 of A-tile and one of B-tile per K-step.
    const int lrow = tid >> 1;             // 0..127
    const int lcol = (tid & 1) * 4;        // 0 or 4
    const float* Ap = A + (size_t)(bm + lrow) * K + lcol;
    const float* Bp = Bm + (size_t)(bn + lrow) * K + lcol;

    float acc[TM][TN];
    #pragma unroll
    for (int i = 0; i < TM; i++)
        #pragma unroll
        for (int j = 0; j < TN; j++) acc[i][j] = 0.f;

    for (int k0 = 0; k0 < K; k0 += BK) {
        float4 av = *(const float4*)(Ap + k0);
        float4 bv = *(const float4*)(Bp + k0);
        As[lcol + 0][lrow] = av.x;
        As[lcol + 1][lrow] = av.y;
        As[lcol + 2][lrow] = av.z;
        As[lcol + 3][lrow] = av.w;
        Bs[lcol + 0][lrow] = bv.x;
        Bs[lcol + 1][lrow] = bv.y;
        Bs[lcol + 2][lrow] = bv.z;
        Bs[lcol + 3][lrow] = bv.w;
        __syncthreads();

        #pragma unroll
        for (int kk = 0; kk < BK; kk++) {
            float a[TM], b[TN];
            #pragma unroll
            for (int i = 0; i < TM; i++) a[i] = As[kk][ty * TM + i];
            #pragma unroll
            for (int j = 0; j < TN; j++) b[j] = Bs[kk][tx * TN + j];
            #pragma unroll
            for (int i = 0; i < TM; i++)
                #pragma unroll
                for (int j = 0; j < TN; j++) acc[i][j] = fmaf(a[i], b[j], acc[i][j]);
        }
        __syncthreads();
    }

    #pragma unroll
    for (int i = 0; i < TM; i++) {
        float* Crow = C + (size_t)(bm + ty * TM + i) * N + bn + tx * TN;
        #pragma unroll
        for (int j = 0; j < TN; j += 4) {
            float4 v = make_float4(acc[i][j], acc[i][j+1], acc[i][j+2], acc[i][j+3]);
            *(float4*)(Crow + j) = v;
        }
    }
}

// ---------------------------------------------------------------------------
// Causal depthwise conv (DC=4) + bias + SiLU(z) gating.
// xz: [MTOK, 2*DI] (u | z). Output ug: [MTOK, DI].
// ---------------------------------------------------------------------------
__global__ void conv_gate_kernel(const float* __restrict__ xz,
                                 const float* __restrict__ conv_w,
                                 const float* __restrict__ conv_b,
                                 float* __restrict__ ug) {
    int idx = blockIdx.x * blockDim.x + threadIdx.x;
    if (idx >= MTOK * DI_) return;
    int i = idx & (DI_ - 1);
    int m = idx >> 11;            // / DI_
    int l = m & (L_ - 1);
    int b = m >> 11;              // / L_

    float acc = conv_b[i];
    const float w0 = conv_w[i * DC_ + 0];
    const float w1 = conv_w[i * DC_ + 1];
    const float w2 = conv_w[i * DC_ + 2];
    const float w3 = conv_w[i * DC_ + 3];
    const float* ubase = xz + (size_t)b * L_ * (2 * DI_) + i;
    // out[l] = sum_j w[j] * u[l - 3 + j]
    if (l >= 3) acc = fmaf(w0, ubase[(size_t)(l - 3) * (2 * DI_)], acc);
    if (l >= 2) acc = fmaf(w1, ubase[(size_t)(l - 2) * (2 * DI_)], acc);
    if (l >= 1) acc = fmaf(w2, ubase[(size_t)(l - 1) * (2 * DI_)], acc);
    acc = fmaf(w3, ubase[(size_t)l * (2 * DI_)], acc);

    float z = xz[(size_t)m * (2 * DI_) + DI_ + i];
    float sig = 1.f / (1.f + __expf(-z));
    ug[idx] = acc * z * sig;
}

// ---------------------------------------------------------------------------
// x-proj: proj[m, 0:33] = ug[m, :] @ x_proj_w[33, DI]^T
// One block per token. Row staged in SMEM; warp per output column.
// ---------------------------------------------------------------------------
__global__ __launch_bounds__(256)
void xproj_kernel(const float* __restrict__ ug,
                  const float* __restrict__ xpw,
                  float* __restrict__ proj) {
    __shared__ float su[DI_];
    int m = blockIdx.x;
    const float* urow = ug + (size_t)m * DI_;
    for (int k = threadIdx.x; k < DI_; k += blockDim.x) su[k] = urow[k];
    __syncthreads();

    int warp = threadIdx.x >> 5;
    int lane = threadIdx.x & 31;
    for (int n = warp; n < NPROJ; n += 8) {
        const float* wrow = xpw + (size_t)n * DI_;
        float sum = 0.f;
        for (int k = lane; k < DI_; k += 32) sum = fmaf(su[k], wrow[k], sum);
        #pragma unroll
        for (int off = 16; off > 0; off >>= 1)
            sum += __shfl_xor_sync(0xffffffffu, sum, off);
        if (lane == 0) proj[(size_t)m * NPROJ + n] = sum;
    }
}

// ---------------------------------------------------------------------------
// Selective scan. One 16-lane group per (b, channel) chain; lane = state s.
// proj row: [ dt_raw | B[0:16] | C[0:16] ].
// ---------------------------------------------------------------------------
__global__ __launch_bounds__(256)
void scan_kernel(const float* __restrict__ ug,
                 const float* __restrict__ proj,
                 const float* __restrict__ dt_w,
                 const float* __restrict__ dt_b,
                 const float* __restrict__ A_log,
                 const float* __restrict__ Dvec,
                 float* __restrict__ y) {
    int g = (blockIdx.x * blockDim.x + threadIdx.x) >> 4;  // 0 .. B*DI-1
    int s = threadIdx.x & 15;
    int b = g >> 11;            // / DI_
    int i = g & (DI_ - 1);

    const float A = -__expf(A_log[i * DS_ + s]);
    const float w = dt_w[i];
    const float bb = dt_b[i];
    const float Dv = Dvec[i];

    const float* pb = proj + (size_t)b * L_ * NPROJ;
    const float* ub = ug + (size_t)b * L_ * DI_ + i;
    float* yb = y + (size_t)b * L_ * DI_ + i;

    float h = 0.f;
    for (int l = 0; l < L_; l++) {
        const float* pr = pb + (size_t)l * NPROJ;
        float p0 = pr[0];
        float Bt = pr[1 + s];
        float Ct = pr[1 + DS_ + s];
        float uv = ub[(size_t)l * DI_];

        float xd = fmaf(p0, w, bb);
        float delta = (xd > 20.f) ? xd : log1pf(__expf(xd));   // softplus
        float dte = __expf(delta);

        h = fmaf(__expf(A * dte), h, Bt * (dte * uv));
        float part = h * Ct;
        part += __shfl_xor_sync(0xffffffffu, part, 1);
        part += __shfl_xor_sync(0xffffffffu, part, 2);
        part += __shfl_xor_sync(0xffffffffu, part, 4);
        part += __shfl_xor_sync(0xffffffffu, part, 8);
        if (s == 0) yb[(size_t)l * DI_] = part + Dv * uv;
    }
}

// ---------------------------------------------------------------------------
extern "C" void kernel_launch(void* const* d_in, const int* in_sizes, int n_in,
                              void* d_out, int out_size) {
    const float* x         = (const float*)d_in[0];  // [B,L,DM]
    const float* in_proj_w = (const float*)d_in[1];  // [2*DI, DM]
    const float* conv_w    = (const float*)d_in[2];  // [DI,1,DC]
    const float* conv_b    = (const float*)d_in[3];  // [DI]
    const float* x_proj_w  = (const float*)d_in[4];  // [33, DI]
    const float* dt_proj_w = (const float*)d_in[5];  // [DI,1]
    const float* dt_proj_b = (const float*)d_in[6];  // [DI]
    const float* A_log     = (const float*)d_in[7];  // [DI,DS]
    const float* Dvec      = (const float*)d_in[8];  // [DI]
    const float* out_proj_w= (const float*)d_in[9];  // [DM, DI]
    float* out = (float*)d_out;                      // [B,L,DM]

    float *xz, *ug, *proj, *y;
    cudaGetSymbolAddress((void**)&xz,   g_xz);
    cudaGetSymbolAddress((void**)&ug,   g_ug);
    cudaGetSymbolAddress((void**)&proj, g_proj);
    cudaGetSymbolAddress((void**)&y,    g_y);

    // 1) in-proj: xz[4096, 4096] = x[4096,1024] @ in_proj_w[4096,1024]^T
    sgemm_nt<<<dim3((2 * DI_) / BN, MTOK / BM), 256>>>(x, in_proj_w, xz,
                                                       MTOK, 2 * DI_, DM_);
    // 2) causal conv + SiLU gate -> ug[4096, 2048]
    conv_gate_kernel<<<(MTOK * DI_ + 255) / 256, 256>>>(xz, conv_w, conv_b, ug);
    // 3) x-proj -> proj[4096, 33]
    xproj_kernel<<<MTOK, 256>>>(ug, x_proj_w, proj);
    // 4) selective scan -> y[4096, 2048]
    scan_kernel<<<(B_ * DI_ * 16) / 256, 256>>>(ug, proj, dt_proj_w, dt_proj_b,
                                                A_log, Dvec, y);
    // 5) out-proj: out[4096, 1024] = y[4096,2048] @ out_proj_w[1024,2048]^T
    sgemm_nt<<<dim3(DM_ / BN, MTOK / BM), 256>>>(y, out_proj_w, out,
                                                 MTOK, DM_, DI_);
}

// round 8
// speedup vs baseline: 1.4152x; 1.4152x over previous
#include <cuda_runtime.h>
#include <cuda_bf16.h>

// Problem constants (fixed by the reference)
#define B_  2
#define L_  2048
#define DM_ 1024
#define DS_ 16
#define DC_ 4
#define DI_ 2048          // EXP_ * DM_
#define MTOK (B_ * L_)    // 4096 tokens
#define NPROJ (2 * DS_ + 1)  // 33

// chunked scan config
#define CH_  32               // chunks per sequence
#define LEN_ (L_ / CH_)       // 64 steps per chunk

typedef unsigned long long u64;

// ---------------- scratch (static device globals; no allocs allowed) -------
__device__ float g_xz[MTOK * 2 * DI_];   // in-proj output [4096, 4096]  (u | z)
__device__ float g_ug[MTOK * DI_];       // gated conv output [4096, 2048]
__device__ float g_proj[MTOK * NPROJ];   // x-proj output [4096, 33]
__device__ float g_y[MTOK * DI_];        // scan output [4096, 2048]
// chunk-scan carries: layout [c][b][i][s]
__device__ float g_E [CH_ * B_ * DI_ * DS_];
__device__ float g_Ap[CH_ * B_ * DI_ * DS_];
__device__ float g_Hs[CH_ * B_ * DI_ * DS_];

// ---------------- packed fp32x2 helpers (sm_103a FFMA2 path) ---------------
__device__ __forceinline__ u64 fma2(u64 a, u64 b, u64 c) {
    u64 d;
    asm("fma.rn.f32x2 %0, %1, %2, %3;" : "=l"(d) : "l"(a), "l"(b), "l"(c));
    return d;
}
__device__ __forceinline__ u64 pack2(float x, float y) {
    u64 d;
    asm("mov.b64 %0, {%1, %2};" : "=l"(d) : "f"(x), "f"(y));
    return d;
}
__device__ __forceinline__ void unpack2(u64 v, float& x, float& y) {
    asm("mov.b64 {%0, %1}, %2;" : "=f"(x), "=f"(y) : "l"(v));
}

// ---------------------------------------------------------------------------
// SGEMM: C[M,N] = A[M,K] @ B[N,K]^T  (both operands K-contiguous, fp32)
// Block tile 128x128, K-tile 8, 256 threads, 8x8 per-thread microtile.
// Inner product uses packed fp32x2 FMA (FFMA2) — exact fp32, 2x fma-pipe rate.
// Next K-tile's global loads issued before the compute block (prefetch).
// ---------------------------------------------------------------------------
#define BM 128
#define BN 128
#define BK 8
#define TM 8
#define TN 8

__global__ __launch_bounds__(256)
void sgemm_nt(const float* __restrict__ A, const float* __restrict__ Bm,
              float* __restrict__ C, int M, int N, int K) {
    __shared__ __align__(16) float As[BK][BM];
    __shared__ __align__(16) float Bs[BK][BN];

    const int bm = blockIdx.y * BM;
    const int bn = blockIdx.x * BN;
    const int tid = threadIdx.x;           // 0..255
    const int tx = tid & 15;               // 0..15 -> N dim
    const int ty = tid >> 4;               // 0..15 -> M dim

    const int lrow = tid >> 1;             // 0..127
    const int lcol = (tid & 1) * 4;        // 0 or 4
    const float* Ap = A + (size_t)(bm + lrow) * K + lcol;
    const float* Bp = Bm + (size_t)(bn + lrow) * K + lcol;

    u64 acc2[TM][TN / 2];
    #pragma unroll
    for (int i = 0; i < TM; i++)
        #pragma unroll
        for (int j = 0; j < TN / 2; j++) acc2[i][j] = 0ull;

    float4 av = *(const float4*)(Ap);
    float4 bv = *(const float4*)(Bp);

    for (int k0 = 0; k0 < K; k0 += BK) {
        As[lcol + 0][lrow] = av.x;
        As[lcol + 1][lrow] = av.y;
        As[lcol + 2][lrow] = av.z;
        As[lcol + 3][lrow] = av.w;
        Bs[lcol + 0][lrow] = bv.x;
        Bs[lcol + 1][lrow] = bv.y;
        Bs[lcol + 2][lrow] = bv.z;
        Bs[lcol + 3][lrow] = bv.w;
        __syncthreads();

        // prefetch next K-tile while this tile computes
        if (k0 + BK < K) {
            av = *(const float4*)(Ap + k0 + BK);
            bv = *(const float4*)(Bp + k0 + BK);
        }

        #pragma unroll
        for (int kk = 0; kk < BK; kk++) {
            float4 a0 = *(const float4*)&As[kk][ty * TM];
            float4 a1 = *(const float4*)&As[kk][ty * TM + 4];
            const longlong2* bp = (const longlong2*)&Bs[kk][tx * TN];
            longlong2 bl0 = bp[0];
            longlong2 bl1 = bp[1];
            u64 b2[4];
            b2[0] = (u64)bl0.x; b2[1] = (u64)bl0.y;
            b2[2] = (u64)bl1.x; b2[3] = (u64)bl1.y;
            float a[TM] = {a0.x, a0.y, a0.z, a0.w, a1.x, a1.y, a1.z, a1.w};
            #pragma unroll
            for (int i = 0; i < TM; i++) {
                u64 aa = pack2(a[i], a[i]);
                #pragma unroll
                for (int j = 0; j < TN / 2; j++)
                    acc2[i][j] = fma2(aa, b2[j], acc2[i][j]);
            }
        }
        __syncthreads();
    }

    #pragma unroll
    for (int i = 0; i < TM; i++) {
        float o[TN];
        #pragma unroll
        for (int j = 0; j < TN / 2; j++) unpack2(acc2[i][j], o[2 * j], o[2 * j + 1]);
        float* Crow = C + (size_t)(bm + ty * TM + i) * N + bn + tx * TN;
        *(float4*)(Crow + 0) = make_float4(o[0], o[1], o[2], o[3]);
        *(float4*)(Crow + 4) = make_float4(o[4], o[5], o[6], o[7]);
    }
}

// ---------------------------------------------------------------------------
// Causal depthwise conv (DC=4) + bias + SiLU(z) gating.
// ---------------------------------------------------------------------------
__global__ void conv_gate_kernel(const float* __restrict__ xz,
                                 const float* __restrict__ conv_w,
                                 const float* __restrict__ conv_b,
                                 float* __restrict__ ug) {
    int idx = blockIdx.x * blockDim.x + threadIdx.x;
    if (idx >= MTOK * DI_) return;
    int i = idx & (DI_ - 1);
    int m = idx >> 11;            // / DI_
    int l = m & (L_ - 1);
    int b = m >> 11;              // / L_

    float acc = conv_b[i];
    const float w0 = conv_w[i * DC_ + 0];
    const float w1 = conv_w[i * DC_ + 1];
    const float w2 = conv_w[i * DC_ + 2];
    const float w3 = conv_w[i * DC_ + 3];
    const float* ubase = xz + (size_t)b * L_ * (2 * DI_) + i;
    if (l >= 3) acc = fmaf(w0, ubase[(size_t)(l - 3) * (2 * DI_)], acc);
    if (l >= 2) acc = fmaf(w1, ubase[(size_t)(l - 2) * (2 * DI_)], acc);
    if (l >= 1) acc = fmaf(w2, ubase[(size_t)(l - 1) * (2 * DI_)], acc);
    acc = fmaf(w3, ubase[(size_t)l * (2 * DI_)], acc);

    float z = xz[(size_t)m * (2 * DI_) + DI_ + i];
    float sig = 1.f / (1.f + __expf(-z));
    ug[idx] = acc * z * sig;
}

// ---------------------------------------------------------------------------
// x-proj: proj[m, 0:33] = ug[m, :] @ x_proj_w[33, DI]^T
// ---------------------------------------------------------------------------
__global__ __launch_bounds__(256)
void xproj_kernel(const float* __restrict__ ug,
                  const float* __restrict__ xpw,
                  float* __restrict__ proj) {
    __shared__ float su[DI_];
    int m = blockIdx.x;
    const float* urow = ug + (size_t)m * DI_;
    for (int k = threadIdx.x; k < DI_; k += blockDim.x) su[k] = urow[k];
    __syncthreads();

    int warp = threadIdx.x >> 5;
    int lane = threadIdx.x & 31;
    for (int n = warp; n < NPROJ; n += 8) {
        const float* wrow = xpw + (size_t)n * DI_;
        float sum = 0.f;
        for (int k = lane; k < DI_; k += 32) sum = fmaf(su[k], wrow[k], sum);
        #pragma unroll
        for (int off = 16; off > 0; off >>= 1)
            sum += __shfl_xor_sync(0xffffffffu, sum, off);
        if (lane == 0) proj[(size_t)m * NPROJ + n] = sum;
    }
}

// ---------------------------------------------------------------------------
// Chunked selective scan.
// Per (b,i,s): h_t = a_t h_{t-1} + B_t[s]*dte_t*u_t,  a_t = exp(A_s * dte_t),
// dte_t = exp(softplus(xd)) == 1 + exp(xd)  (exact identity).
// a_t < 1 always (A_s < 0, dte_t > 0) -> contractive -> chunked recombination
// is numerically stable.
// Pass 1: per chunk, zero-start end state E and decay product Aprod.
// Pass 2: sequential combine over CH_ chunks -> true chunk-start states Hs.
// Pass 3: re-scan each chunk from Hs, emit y.
// ---------------------------------------------------------------------------
__global__ __launch_bounds__(256)
void scan_pass1(const float* __restrict__ ug, const float* __restrict__ proj,
                const float* __restrict__ dt_w, const float* __restrict__ dt_b,
                const float* __restrict__ A_log,
                float* __restrict__ E, float* __restrict__ Ap) {
    __shared__ float sp[LEN_ * NPROJ];
    const int i = blockIdx.x * 256 + threadIdx.x;
    const int c = blockIdx.y;
    const int b = blockIdx.z;

    const float* pchunk = proj + ((size_t)b * L_ + (size_t)c * LEN_) * NPROJ;
    for (int k = threadIdx.x; k < LEN_ * NPROJ; k += 256) sp[k] = pchunk[k];
    __syncthreads();

    const float w  = dt_w[i];
    const float bb = dt_b[i];
    float A[DS_];
    #pragma unroll
    for (int s = 0; s < DS_; s++) A[s] = -__expf(A_log[i * DS_ + s]);

    float h[DS_], ap[DS_];
    #pragma unroll
    for (int s = 0; s < DS_; s++) { h[s] = 0.f; ap[s] = 1.f; }

    const float* up = ug + ((size_t)b * L_ + (size_t)c * LEN_) * DI_ + i;
    #pragma unroll 2
    for (int l = 0; l < LEN_; l++) {
        const float* pr = &sp[l * NPROJ];
        float p0 = pr[0];
        float uv = up[(size_t)l * DI_];
        float dte = 1.f + __expf(fmaf(p0, w, bb));
        float du = dte * uv;
        #pragma unroll
        for (int s = 0; s < DS_; s++) {
            float ab = __expf(A[s] * dte);
            h[s] = fmaf(ab, h[s], pr[1 + s] * du);
            ap[s] *= ab;
        }
    }

    size_t base = ((((size_t)c * B_ + b) * DI_) + i) * DS_;
    #pragma unroll
    for (int s = 0; s < DS_; s += 4) {
        *(float4*)(E  + base + s) = make_float4(h[s],  h[s+1],  h[s+2],  h[s+3]);
        *(float4*)(Ap + base + s) = make_float4(ap[s], ap[s+1], ap[s+2], ap[s+3]);
    }
}

__global__ __launch_bounds__(256)
void scan_pass2(const float* __restrict__ E, const float* __restrict__ Ap,
                float* __restrict__ Hs) {
    const int t = blockIdx.x * 256 + threadIdx.x;   // (b,i,s) flattened
    const size_t stride = (size_t)B_ * DI_ * DS_;
    float h = 0.f;
    #pragma unroll 4
    for (int c = 0; c < CH_; c++) {
        size_t idx = (size_t)c * stride + t;
        Hs[idx] = h;
        h = fmaf(Ap[idx], h, E[idx]);
    }
}

__global__ __launch_bounds__(256)
void scan_pass3(const float* __restrict__ ug, const float* __restrict__ proj,
                const float* __restrict__ dt_w, const float* __restrict__ dt_b,
                const float* __restrict__ A_log, const float* __restrict__ Dvec,
                const float* __restrict__ Hs, float* __restrict__ y) {
    __shared__ float sp[LEN_ * NPROJ];
    const int i = blockIdx.x * 256 + threadIdx.x;
    const int c = blockIdx.y;
    const int b = blockIdx.z;

    const float* pchunk = proj + ((size_t)b * L_ + (size_t)c * LEN_) * NPROJ;
    for (int k = threadIdx.x; k < LEN_ * NPROJ; k += 256) sp[k] = pchunk[k];
    __syncthreads();

    const float w  = dt_w[i];
    const float bb = dt_b[i];
    const float Dv = Dvec[i];
    float A[DS_];
    #pragma unroll
    for (int s = 0; s < DS_; s++) A[s] = -__expf(A_log[i * DS_ + s]);

    float h[DS_];
    size_t base = ((((size_t)c * B_ + b) * DI_) + i) * DS_;
    #pragma unroll
    for (int s = 0; s < DS_; s += 4) {
        float4 v = *(const float4*)(Hs + base + s);
        h[s] = v.x; h[s+1] = v.y; h[s+2] = v.z; h[s+3] = v.w;
    }

    const float* up = ug + ((size_t)b * L_ + (size_t)c * LEN_) * DI_ + i;
    float* yp = y + ((size_t)b * L_ + (size_t)c * LEN_) * DI_ + i;
    #pragma unroll 2
    for (int l = 0; l < LEN_; l++) {
        const float* pr = &sp[l * NPROJ];
        float p0 = pr[0];
        float uv = up[(size_t)l * DI_];
        float dte = 1.f + __expf(fmaf(p0, w, bb));
        float du = dte * uv;
        float acc = Dv * uv;
        #pragma unroll
        for (int s = 0; s < DS_; s++) {
            float ab = __expf(A[s] * dte);
            h[s] = fmaf(ab, h[s], pr[1 + s] * du);
            acc = fmaf(pr[1 + DS_ + s], h[s], acc);
        }
        yp[(size_t)l * DI_] = acc;
    }
}

// ---------------------------------------------------------------------------
extern "C" void kernel_launch(void* const* d_in, const int* in_sizes, int n_in,
                              void* d_out, int out_size) {
    const float* x         = (const float*)d_in[0];  // [B,L,DM]
    const float* in_proj_w = (const float*)d_in[1];  // [2*DI, DM]
    const float* conv_w    = (const float*)d_in[2];  // [DI,1,DC]
    const float* conv_b    = (const float*)d_in[3];  // [DI]
    const float* x_proj_w  = (const float*)d_in[4];  // [33, DI]
    const float* dt_proj_w = (const float*)d_in[5];  // [DI,1]
    const float* dt_proj_b = (const float*)d_in[6];  // [DI]
    const float* A_log     = (const float*)d_in[7];  // [DI,DS]
    const float* Dvec      = (const float*)d_in[8];  // [DI]
    const float* out_proj_w= (const float*)d_in[9];  // [DM, DI]
    float* out = (float*)d_out;                      // [B,L,DM]

    float *xz, *ug, *proj, *y, *E, *Ap, *Hs;
    cudaGetSymbolAddress((void**)&xz,   g_xz);
    cudaGetSymbolAddress((void**)&ug,   g_ug);
    cudaGetSymbolAddress((void**)&proj, g_proj);
    cudaGetSymbolAddress((void**)&y,    g_y);
    cudaGetSymbolAddress((void**)&E,    g_E);
    cudaGetSymbolAddress((void**)&Ap,   g_Ap);
    cudaGetSymbolAddress((void**)&Hs,   g_Hs);

    // 1) in-proj: xz[4096, 4096] = x @ in_proj_w^T
    sgemm_nt<<<dim3((2 * DI_) / BN, MTOK / BM), 256>>>(x, in_proj_w, xz,
                                                       MTOK, 2 * DI_, DM_);
    // 2) causal conv + SiLU gate -> ug[4096, 2048]
    conv_gate_kernel<<<(MTOK * DI_ + 255) / 256, 256>>>(xz, conv_w, conv_b, ug);
    // 3) x-proj -> proj[4096, 33]
    xproj_kernel<<<MTOK, 256>>>(ug, x_proj_w, proj);
    // 4) chunked selective scan -> y[4096, 2048]
    dim3 sgrid(DI_ / 256, CH_, B_);
    scan_pass1<<<sgrid, 256>>>(ug, proj, dt_proj_w, dt_proj_b, A_log, E, Ap);
    scan_pass2<<<(B_ * DI_ * DS_) / 256, 256>>>(E, Ap, Hs);
    scan_pass3<<<sgrid, 256>>>(ug, proj, dt_proj_w, dt_proj_b, A_log, Dvec,
                               Hs, y);
    // 5) out-proj: out[4096, 1024] = y @ out_proj_w^T
    sgemm_nt<<<dim3(DM_ / BN, MTOK / BM), 256>>>(y, out_proj_w, out,
                                                 MTOK, DM_, DI_);
}

// round 10
// speedup vs baseline: 2.2858x; 1.6152x over previous
#include <cuda_runtime.h>
#include <cuda_bf16.h>
#include <cstdint>

// Problem constants (fixed by the reference)
#define B_  2
#define L_  2048
#define DM_ 1024
#define DS_ 16
#define DC_ 4
#define DI_ 2048          // EXP_ * DM_
#define MTOK (B_ * L_)    // 4096 tokens
#define NPROJ (2 * DS_ + 1)  // 33

// chunked scan config
#define CH_  32               // chunks per sequence
#define LEN_ (L_ / CH_)       // 64 steps per chunk

// ---------------- scratch (static device globals; no allocs allowed) -------
__device__ float g_xz[MTOK * 2 * DI_];   // in-proj output [4096, 4096]  (u | z)
__device__ float g_ug[MTOK * DI_];       // gated conv output [4096, 2048]
__device__ float g_proj[MTOK * NPROJ];   // x-proj output [4096, 33]
__device__ float g_y[MTOK * DI_];        // scan output [4096, 2048]
// chunk-scan carries: layout [c][b][i][s]
__device__ float g_E [CH_ * B_ * DI_ * DS_];
__device__ float g_Ap[CH_ * B_ * DI_ * DS_];
__device__ float g_Hs[CH_ * B_ * DI_ * DS_];
// bf16 split buffers (hi/lo) for tensor-core GEMMs
__device__ __nv_bfloat16 g_xh [MTOK * DM_];
__device__ __nv_bfloat16 g_xl [MTOK * DM_];
__device__ __nv_bfloat16 g_w1h[2 * DI_ * DM_];
__device__ __nv_bfloat16 g_w1l[2 * DI_ * DM_];
__device__ __nv_bfloat16 g_yh [MTOK * DI_];
__device__ __nv_bfloat16 g_yl [MTOK * DI_];
__device__ __nv_bfloat16 g_w2h[DM_ * DI_];
__device__ __nv_bfloat16 g_w2l[DM_ * DI_];

// ---------------------------------------------------------------------------
// fp32 -> (hi, lo) bf16 split:  v ≈ hi + lo,  |lo| <= 2^-9 |v|
// ---------------------------------------------------------------------------
__global__ void split_bf16_kernel(const float* __restrict__ src,
                                  __nv_bfloat16* __restrict__ hi,
                                  __nv_bfloat16* __restrict__ lo, int n) {
    int idx = blockIdx.x * blockDim.x + threadIdx.x;
    if (idx >= n) return;
    float v = src[idx];
    __nv_bfloat16 h = __float2bfloat16(v);
    hi[idx] = h;
    lo[idx] = __float2bfloat16(v - __bfloat162float(h));
}

// ---------------------------------------------------------------------------
// Split-precision bf16 tensor-core GEMM:
//   C[M,N] = A @ W^T, reconstructed as Ah*Wh + Ah*Wl + Al*Wh  (fp32 accum).
// A*: [M,K] bf16 row-major; W*: [N,K] bf16 row-major.
// Block 256 thr, tile 128x128, K-step 32. Warps 2x4, warptile 64x32.
// mma.sync.m16n8k16.row.col.f32.bf16.bf16.f32; fragments loaded per the PTX
// documented lane layout (A and B both k-contiguous pairs -> plain LDS.32).
// ---------------------------------------------------------------------------
#define GKT 32            // K elements per smem tile
#define GKP 40            // padded row length (80B rows: 16B-aligned, no LDS conflicts)

__device__ __forceinline__ void mma_bf16(float& d0, float& d1, float& d2, float& d3,
                                         uint32_t a0, uint32_t a1, uint32_t a2, uint32_t a3,
                                         uint32_t b0, uint32_t b1) {
    asm volatile(
        "mma.sync.aligned.m16n8k16.row.col.f32.bf16.bf16.f32 "
        "{%0,%1,%2,%3}, {%4,%5,%6,%7}, {%8,%9}, {%0,%1,%2,%3};"
        : "+f"(d0), "+f"(d1), "+f"(d2), "+f"(d3)
        : "r"(a0), "r"(a1), "r"(a2), "r"(a3), "r"(b0), "r"(b1));
}

__global__ __launch_bounds__(256)
void gemm_bf16s(const __nv_bfloat16* __restrict__ Ah,
                const __nv_bfloat16* __restrict__ Al,
                const __nv_bfloat16* __restrict__ Wh,
                const __nv_bfloat16* __restrict__ Wl,
                float* __restrict__ C, int M, int N, int K) {
    __shared__ __align__(16) __nv_bfloat16 sAh[128][GKP];
    __shared__ __align__(16) __nv_bfloat16 sAl[128][GKP];
    __shared__ __align__(16) __nv_bfloat16 sWh[128][GKP];
    __shared__ __align__(16) __nv_bfloat16 sWl[128][GKP];

    const int tid  = threadIdx.x;
    const int bm   = blockIdx.y * 128;
    const int bn   = blockIdx.x * 128;
    const int wid  = tid >> 5;
    const int lane = tid & 31;
    const int wm   = (wid >> 2) * 64;    // warp M offset within block: 0 or 64
    const int wn   = (wid & 3) * 32;     // warp N offset within block: 0..96
    const int g    = lane >> 2;          // groupID 0..7
    const int t    = lane & 3;           // thread in group

    // global->smem loader: 2 threads per row, 2x uint4 (8 bf16) each
    const int lr = tid >> 1;             // row 0..127
    const int lc = (tid & 1) * 2;        // uint4 chunk 0 or 2

    float acc[4][4][4];                  // [m-tile][n-tile][c0..c3]
    #pragma unroll
    for (int i = 0; i < 4; i++)
        #pragma unroll
        for (int j = 0; j < 4; j++)
            #pragma unroll
            for (int c = 0; c < 4; c++) acc[i][j][c] = 0.f;

    for (int k0 = 0; k0 < K; k0 += GKT) {
        // load 128x32 tiles of all 4 operands
        {
            const uint4* pa_h = (const uint4*)(Ah + (size_t)(bm + lr) * K + k0);
            const uint4* pa_l = (const uint4*)(Al + (size_t)(bm + lr) * K + k0);
            const uint4* pw_h = (const uint4*)(Wh + (size_t)(bn + lr) * K + k0);
            const uint4* pw_l = (const uint4*)(Wl + (size_t)(bn + lr) * K + k0);
            #pragma unroll
            for (int j = 0; j < 2; j++) {
                *(uint4*)&sAh[lr][(lc + j) * 8] = pa_h[lc + j];
                *(uint4*)&sAl[lr][(lc + j) * 8] = pa_l[lc + j];
                *(uint4*)&sWh[lr][(lc + j) * 8] = pw_h[lc + j];
                *(uint4*)&sWl[lr][(lc + j) * 8] = pw_l[lc + j];
            }
        }
        __syncthreads();

        #pragma unroll
        for (int ks = 0; ks < GKT; ks += 16) {
            uint32_t ah[4][4], al[4][4], bh[4][2], bl[4][2];
            #pragma unroll
            for (int mt = 0; mt < 4; mt++) {
                int r0 = wm + mt * 16 + g;
                ah[mt][0] = *(const uint32_t*)&sAh[r0    ][ks + t * 2];
                ah[mt][1] = *(const uint32_t*)&sAh[r0 + 8][ks + t * 2];
                ah[mt][2] = *(const uint32_t*)&sAh[r0    ][ks + t * 2 + 8];
                ah[mt][3] = *(const uint32_t*)&sAh[r0 + 8][ks + t * 2 + 8];
                al[mt][0] = *(const uint32_t*)&sAl[r0    ][ks + t * 2];
                al[mt][1] = *(const uint32_t*)&sAl[r0 + 8][ks + t * 2];
                al[mt][2] = *(const uint32_t*)&sAl[r0    ][ks + t * 2 + 8];
                al[mt][3] = *(const uint32_t*)&sAl[r0 + 8][ks + t * 2 + 8];
            }
            #pragma unroll
            for (int nt = 0; nt < 4; nt++) {
                int r0 = wn + nt * 8 + g;
                bh[nt][0] = *(const uint32_t*)&sWh[r0][ks + t * 2];
                bh[nt][1] = *(const uint32_t*)&sWh[r0][ks + t * 2 + 8];
                bl[nt][0] = *(const uint32_t*)&sWl[r0][ks + t * 2];
                bl[nt][1] = *(const uint32_t*)&sWl[r0][ks + t * 2 + 8];
            }
            #pragma unroll
            for (int mt = 0; mt < 4; mt++)
                #pragma unroll
                for (int nt = 0; nt < 4; nt++) {
                    float* d = acc[mt][nt];
                    mma_bf16(d[0], d[1], d[2], d[3],
                             ah[mt][0], ah[mt][1], ah[mt][2], ah[mt][3],
                             bh[nt][0], bh[nt][1]);
                    mma_bf16(d[0], d[1], d[2], d[3],
                             ah[mt][0], ah[mt][1], ah[mt][2], ah[mt][3],
                             bl[nt][0], bl[nt][1]);
                    mma_bf16(d[0], d[1], d[2], d[3],
                             al[mt][0], al[mt][1], al[mt][2], al[mt][3],
                             bh[nt][0], bh[nt][1]);
                }
        }
        __syncthreads();
    }

    // epilogue: c0/c1 at (row, col), c2/c3 at (row+8, col); col = even -> float2
    #pragma unroll
    for (int mt = 0; mt < 4; mt++) {
        #pragma unroll
        for (int nt = 0; nt < 4; nt++) {
            int row = bm + wm + mt * 16 + g;
            int col = bn + wn + nt * 8 + t * 2;
            float* d = acc[mt][nt];
            *(float2*)&C[(size_t)row * N + col]       = make_float2(d[0], d[1]);
            *(float2*)&C[(size_t)(row + 8) * N + col] = make_float2(d[2], d[3]);
        }
    }
}

// ---------------------------------------------------------------------------
// Causal depthwise conv (DC=4) + bias + SiLU(z) gating.
// ---------------------------------------------------------------------------
__global__ void conv_gate_kernel(const float* __restrict__ xz,
                                 const float* __restrict__ conv_w,
                                 const float* __restrict__ conv_b,
                                 float* __restrict__ ug) {
    int idx = blockIdx.x * blockDim.x + threadIdx.x;
    if (idx >= MTOK * DI_) return;
    int i = idx & (DI_ - 1);
    int m = idx >> 11;            // / DI_
    int l = m & (L_ - 1);
    int b = m >> 11;              // / L_

    float acc = conv_b[i];
    const float w0 = conv_w[i * DC_ + 0];
    const float w1 = conv_w[i * DC_ + 1];
    const float w2 = conv_w[i * DC_ + 2];
    const float w3 = conv_w[i * DC_ + 3];
    const float* ubase = xz + (size_t)b * L_ * (2 * DI_) + i;
    if (l >= 3) acc = fmaf(w0, ubase[(size_t)(l - 3) * (2 * DI_)], acc);
    if (l >= 2) acc = fmaf(w1, ubase[(size_t)(l - 2) * (2 * DI_)], acc);
    if (l >= 1) acc = fmaf(w2, ubase[(size_t)(l - 1) * (2 * DI_)], acc);
    acc = fmaf(w3, ubase[(size_t)l * (2 * DI_)], acc);

    float z = xz[(size_t)m * (2 * DI_) + DI_ + i];
    float sig = 1.f / (1.f + __expf(-z));
    ug[idx] = acc * z * sig;
}

// ---------------------------------------------------------------------------
// x-proj: proj[m, 0:33] = ug[m, :] @ x_proj_w[33, DI]^T
// ---------------------------------------------------------------------------
__global__ __launch_bounds__(256)
void xproj_kernel(const float* __restrict__ ug,
                  const float* __restrict__ xpw,
                  float* __restrict__ proj) {
    __shared__ float su[DI_];
    int m = blockIdx.x;
    const float* urow = ug + (size_t)m * DI_;
    for (int k = threadIdx.x; k < DI_; k += blockDim.x) su[k] = urow[k];
    __syncthreads();

    int warp = threadIdx.x >> 5;
    int lane = threadIdx.x & 31;
    for (int n = warp; n < NPROJ; n += 8) {
        const float* wrow = xpw + (size_t)n * DI_;
        float sum = 0.f;
        for (int k = lane; k < DI_; k += 32) sum = fmaf(su[k], wrow[k], sum);
        #pragma unroll
        for (int off = 16; off > 0; off >>= 1)
            sum += __shfl_xor_sync(0xffffffffu, sum, off);
        if (lane == 0) proj[(size_t)m * NPROJ + n] = sum;
    }
}

// ---------------------------------------------------------------------------
// Chunked selective scan (validated R8: pass1 = 70.9us).
// dte = exp(softplus(xd)) == 1 + exp(xd); recurrence contractive -> chunked
// recombination exact up to fp32 reassociation.
// ---------------------------------------------------------------------------
__global__ __launch_bounds__(256)
void scan_pass1(const float* __restrict__ ug, const float* __restrict__ proj,
                const float* __restrict__ dt_w, const float* __restrict__ dt_b,
                const float* __restrict__ A_log,
                float* __restrict__ E, float* __restrict__ Ap) {
    __shared__ float sp[LEN_ * NPROJ];
    const int i = blockIdx.x * 256 + threadIdx.x;
    const int c = blockIdx.y;
    const int b = blockIdx.z;

    const float* pchunk = proj + ((size_t)b * L_ + (size_t)c * LEN_) * NPROJ;
    for (int k = threadIdx.x; k < LEN_ * NPROJ; k += 256) sp[k] = pchunk[k];
    __syncthreads();

    const float w  = dt_w[i];
    const float bb = dt_b[i];
    float A[DS_];
    #pragma unroll
    for (int s = 0; s < DS_; s++) A[s] = -__expf(A_log[i * DS_ + s]);

    float h[DS_], ap[DS_];
    #pragma unroll
    for (int s = 0; s < DS_; s++) { h[s] = 0.f; ap[s] = 1.f; }

    const float* up = ug + ((size_t)b * L_ + (size_t)c * LEN_) * DI_ + i;
    #pragma unroll 2
    for (int l = 0; l < LEN_; l++) {
        const float* pr = &sp[l * NPROJ];
        float p0 = pr[0];
        float uv = up[(size_t)l * DI_];
        float dte = 1.f + __expf(fmaf(p0, w, bb));
        float du = dte * uv;
        #pragma unroll
        for (int s = 0; s < DS_; s++) {
            float ab = __expf(A[s] * dte);
            h[s] = fmaf(ab, h[s], pr[1 + s] * du);
            ap[s] *= ab;
        }
    }

    size_t base = ((((size_t)c * B_ + b) * DI_) + i) * DS_;
    #pragma unroll
    for (int s = 0; s < DS_; s += 4) {
        *(float4*)(E  + base + s) = make_float4(h[s],  h[s+1],  h[s+2],  h[s+3]);
        *(float4*)(Ap + base + s) = make_float4(ap[s], ap[s+1], ap[s+2], ap[s+3]);
    }
}

__global__ __launch_bounds__(256)
void scan_pass2(const float* __restrict__ E, const float* __restrict__ Ap,
                float* __restrict__ Hs) {
    const int t = blockIdx.x * 256 + threadIdx.x;   // (b,i,s) flattened
    const size_t stride = (size_t)B_ * DI_ * DS_;
    float h = 0.f;
    #pragma unroll 4
    for (int c = 0; c < CH_; c++) {
        size_t idx = (size_t)c * stride + t;
        Hs[idx] = h;
        h = fmaf(Ap[idx], h, E[idx]);
    }
}

__global__ __launch_bounds__(256)
void scan_pass3(const float* __restrict__ ug, const float* __restrict__ proj,
                const float* __restrict__ dt_w, const float* __restrict__ dt_b,
                const float* __restrict__ A_log, const float* __restrict__ Dvec,
                const float* __restrict__ Hs, float* __restrict__ y) {
    __shared__ float sp[LEN_ * NPROJ];
    const int i = blockIdx.x * 256 + threadIdx.x;
    const int c = blockIdx.y;
    const int b = blockIdx.z;

    const float* pchunk = proj + ((size_t)b * L_ + (size_t)c * LEN_) * NPROJ;
    for (int k = threadIdx.x; k < LEN_ * NPROJ; k += 256) sp[k] = pchunk[k];
    __syncthreads();

    const float w  = dt_w[i];
    const float bb = dt_b[i];
    const float Dv = Dvec[i];
    float A[DS_];
    #pragma unroll
    for (int s = 0; s < DS_; s++) A[s] = -__expf(A_log[i * DS_ + s]);

    float h[DS_];
    size_t base = ((((size_t)c * B_ + b) * DI_) + i) * DS_;
    #pragma unroll
    for (int s = 0; s < DS_; s += 4) {
        float4 v = *(const float4*)(Hs + base + s);
        h[s] = v.x; h[s+1] = v.y; h[s+2] = v.z; h[s+3] = v.w;
    }

    const float* up = ug + ((size_t)b * L_ + (size_t)c * LEN_) * DI_ + i;
    float* yp = y + ((size_t)b * L_ + (size_t)c * LEN_) * DI_ + i;
    #pragma unroll 2
    for (int l = 0; l < LEN_; l++) {
        const float* pr = &sp[l * NPROJ];
        float p0 = pr[0];
        float uv = up[(size_t)l * DI_];
        float dte = 1.f + __expf(fmaf(p0, w, bb));
        float du = dte * uv;
        float acc = Dv * uv;
        #pragma unroll
        for (int s = 0; s < DS_; s++) {
            float ab = __expf(A[s] * dte);
            h[s] = fmaf(ab, h[s], pr[1 + s] * du);
            acc = fmaf(pr[1 + DS_ + s], h[s], acc);
        }
        yp[(size_t)l * DI_] = acc;
    }
}

// ---------------------------------------------------------------------------
extern "C" void kernel_launch(void* const* d_in, const int* in_sizes, int n_in,
                              void* d_out, int out_size) {
    const float* x         = (const float*)d_in[0];  // [B,L,DM]
    const float* in_proj_w = (const float*)d_in[1];  // [2*DI, DM]
    const float* conv_w    = (const float*)d_in[2];  // [DI,1,DC]
    const float* conv_b    = (const float*)d_in[3];  // [DI]
    const float* x_proj_w  = (const float*)d_in[4];  // [33, DI]
    const float* dt_proj_w = (const float*)d_in[5];  // [DI,1]
    const float* dt_proj_b = (const float*)d_in[6];  // [DI]
    const float* A_log     = (const float*)d_in[7];  // [DI,DS]
    const float* Dvec      = (const float*)d_in[8];  // [DI]
    const float* out_proj_w= (const float*)d_in[9];  // [DM, DI]
    float* out = (float*)d_out;                      // [B,L,DM]

    float *xz, *ug, *proj, *y, *E, *Ap, *Hs;
    __nv_bfloat16 *xh, *xl, *w1h, *w1l, *yh, *yl, *w2h, *w2l;
    cudaGetSymbolAddress((void**)&xz,   g_xz);
    cudaGetSymbolAddress((void**)&ug,   g_ug);
    cudaGetSymbolAddress((void**)&proj, g_proj);
    cudaGetSymbolAddress((void**)&y,    g_y);
    cudaGetSymbolAddress((void**)&E,    g_E);
    cudaGetSymbolAddress((void**)&Ap,   g_Ap);
    cudaGetSymbolAddress((void**)&Hs,   g_Hs);
    cudaGetSymbolAddress((void**)&xh,   g_xh);
    cudaGetSymbolAddress((void**)&xl,   g_xl);
    cudaGetSymbolAddress((void**)&w1h,  g_w1h);
    cudaGetSymbolAddress((void**)&w1l,  g_w1l);
    cudaGetSymbolAddress((void**)&yh,   g_yh);
    cudaGetSymbolAddress((void**)&yl,   g_yl);
    cudaGetSymbolAddress((void**)&w2h,  g_w2h);
    cudaGetSymbolAddress((void**)&w2l,  g_w2l);

    // 0) bf16 splits for GEMM1 operands
    split_bf16_kernel<<<(MTOK * DM_ + 255) / 256, 256>>>(x, xh, xl, MTOK * DM_);
    split_bf16_kernel<<<(2 * DI_ * DM_ + 255) / 256, 256>>>(in_proj_w, w1h, w1l,
                                                            2 * DI_ * DM_);
    // 1) in-proj: xz[4096, 4096] = x @ in_proj_w^T  (tensor cores, split bf16)
    gemm_bf16s<<<dim3((2 * DI_) / 128, MTOK / 128), 256>>>(xh, xl, w1h, w1l, xz,
                                                           MTOK, 2 * DI_, DM_);
    // 2) causal conv + SiLU gate -> ug[4096, 2048]
    conv_gate_kernel<<<(MTOK * DI_ + 255) / 256, 256>>>(xz, conv_w, conv_b, ug);
    // 3) x-proj -> proj[4096, 33]
    xproj_kernel<<<MTOK, 256>>>(ug, x_proj_w, proj);
    // 4) chunked selective scan -> y[4096, 2048]
    dim3 sgrid(DI_ / 256, CH_, B_);
    scan_pass1<<<sgrid, 256>>>(ug, proj, dt_proj_w, dt_proj_b, A_log, E, Ap);
    scan_pass2<<<(B_ * DI_ * DS_) / 256, 256>>>(E, Ap, Hs);
    scan_pass3<<<sgrid, 256>>>(ug, proj, dt_proj_w, dt_proj_b, A_log, Dvec,
                               Hs, y);
    // 5) bf16 splits for GEMM2 operands
    split_bf16_kernel<<<(MTOK * DI_ + 255) / 256, 256>>>(y, yh, yl, MTOK * DI_);
    split_bf16_kernel<<<(DM_ * DI_ + 255) / 256, 256>>>(out_proj_w, w2h, w2l,
                                                        DM_ * DI_);
    // 6) out-proj: out[4096, 1024] = y @ out_proj_w^T (tensor cores, split bf16)
    gemm_bf16s<<<dim3(DM_ / 128, MTOK / 128), 256>>>(yh, yl, w2h, w2l, out,
                                                     MTOK, DM_, DI_);
}